// round 16
// baseline (speedup 1.0000x reference)
#include <cuda_runtime.h>
#include <cuda_fp16.h>
#include <cstdint>

// Problem constants
#define NB 2
#define NS 2048
#define NE 1024
#define NH 16
#define ND 64
#define NM (NB * NS)   // 4096 rows

// ---------------------------------------------------------------------------
// Static device scratch (fp16 operands; fp32 accumulation for proj/PV)
// ---------------------------------------------------------------------------
__device__ __align__(16) __half g_xh[(size_t)NM * NE];        // fp16 x
__device__ __align__(16) __half g_wh[3][(size_t)NE * NE];     // fp16 Wq/Wk/Wv
__device__ __align__(16) __half g_qh[(size_t)NM * NE];        // Q*ESCALE [b,h,s,d]
__device__ __align__(16) __half g_kh[(size_t)NM * NE];        // K [b,h,s,d]
__device__ __align__(16) __half g_vh[(size_t)NM * NE];        // V [b,h,s,d]

// ---------------------------------------------------------------------------
// Helpers
// ---------------------------------------------------------------------------
__device__ __forceinline__ uint32_t smem_u32(const void* p) {
    uint32_t a;
    asm("{ .reg .u64 t; cvta.to.shared.u64 t, %1; cvt.u32.u64 %0, t; }"
        : "=r"(a) : "l"(p));
    return a;
}

__device__ __forceinline__ void cp_async16(uint32_t dst, const void* src) {
    asm volatile("cp.async.cg.shared.global [%0], [%1], 16;"
                 :: "r"(dst), "l"(src) : "memory");
}
#define CP_COMMIT() asm volatile("cp.async.commit_group;" ::: "memory")
#define CP_WAIT(n)  asm volatile("cp.async.wait_group %0;" :: "n"(n) : "memory")

__device__ __forceinline__ uint32_t pack_h2(float lo, float hi) {
    uint32_t r;
    asm("cvt.rn.f16x2.f32 %0, %1, %2;" : "=r"(r) : "f"(hi), "f"(lo));
    return r;
}

// half2 exp2 on MUFU: two exps per instruction
__device__ __forceinline__ uint32_t h2ex2(uint32_t x) {
    uint32_t r;
    asm("ex2.approx.f16x2 %0, %1;" : "=r"(r) : "r"(x));
    return r;
}

// m16n8k16 fp16 mma, fp32 accumulate: D = A*B + D
__device__ __forceinline__ void mma_f16(float* c, uint32_t a0, uint32_t a1,
                                        uint32_t a2, uint32_t a3,
                                        uint32_t b0, uint32_t b1) {
    asm volatile(
        "mma.sync.aligned.m16n8k16.row.col.f32.f16.f16.f32 "
        "{%0,%1,%2,%3}, {%4,%5,%6,%7}, {%8,%9}, {%0,%1,%2,%3};"
        : "+f"(c[0]), "+f"(c[1]), "+f"(c[2]), "+f"(c[3])
        : "r"(a0), "r"(a1), "r"(a2), "r"(a3), "r"(b0), "r"(b1));
}

// m16n8k16 fp16 mma, fp16 accumulate: D = A*B + D.
// D layout: c[0] = f16x2 {row g, cols 2tg,2tg+1}, c[1] = same for row g+8 —
// identical to the fp16 A-fragment layout, so S comes out pre-packed for PV.
__device__ __forceinline__ void mma_f16c(uint32_t* c, uint32_t a0, uint32_t a1,
                                         uint32_t a2, uint32_t a3,
                                         uint32_t b0, uint32_t b1) {
    asm volatile(
        "mma.sync.aligned.m16n8k16.row.col.f16.f16.f16.f16 "
        "{%0,%1}, {%2,%3,%4,%5}, {%6,%7}, {%0,%1};"
        : "+r"(c[0]), "+r"(c[1])
        : "r"(a0), "r"(a1), "r"(a2), "r"(a3), "r"(b0), "r"(b1));
}

#define LDSM_X4(r, addr) \
    asm volatile("ldmatrix.sync.aligned.m8n8.x4.shared.b16 {%0,%1,%2,%3}, [%4];" \
                 : "=r"((r)[0]), "=r"((r)[1]), "=r"((r)[2]), "=r"((r)[3]) \
                 : "r"(addr))

#define LDSM_X4T(r, addr) \
    asm volatile("ldmatrix.sync.aligned.m8n8.x4.trans.shared.b16 {%0,%1,%2,%3}, [%4];" \
                 : "=r"((r)[0]), "=r"((r)[1]), "=r"((r)[2]), "=r"((r)[3]) \
                 : "r"(addr))

// ---------------------------------------------------------------------------
// Rounding pre-pass: fp32 -> fp16 (rn); single 8-byte store per float4.
// ---------------------------------------------------------------------------
#define XN4 (NM * NE / 4)
#define WN4 (NE * NE / 4)
#define TOTAL4 (XN4 + 3 * WN4)   // 1835008

__global__ __launch_bounds__(256) void round_f16_kernel(
    const float4* __restrict__ x,  uint2* __restrict__ xh,
    const float4* __restrict__ w0, const float4* __restrict__ w1,
    const float4* __restrict__ w2, uint2* __restrict__ wh)
{
#pragma unroll
    for (int u = 0; u < 2; u++) {
        int i = blockIdx.x * 512 + u * 256 + threadIdx.x;
        if (i >= TOTAL4) return;
        const float4* src;
        uint2* dst;
        if (i < XN4) {
            src = x + i; dst = xh + i;
        } else {
            int j = i - XN4;
            int wsel = j / WN4;
            int off = j - wsel * WN4;
            src = ((wsel == 0) ? w0 : (wsel == 1) ? w1 : w2) + off;
            dst = wh + (size_t)wsel * WN4 + off;
        }
        float4 v = *src;
        uint2 o;
        o.x = pack_h2(v.x, v.y);
        o.y = pack_h2(v.z, v.w);
        *dst = o;
    }
}

// ---------------------------------------------------------------------------
// Fused QKV projection, fp16 m16n8k16, LDSM loads, 3-stage cp.async pipeline,
// single barrier per K-step, K-step = 64 halves. (Round-13, known good.)
// ---------------------------------------------------------------------------
#define KSTEP 64
#define RPADH 72
#define TILE_H (128 * RPADH)
#define PROJ_STAGES 3
#define PROJ_SMEM (PROJ_STAGES * 2 * TILE_H * (int)sizeof(__half))  // 110592 B
#define ESCALE_F 0.1803368801111601f

__global__ __launch_bounds__(256, 2) void proj_mma_kernel(
    const __half* __restrict__ A,
    const __half* __restrict__ Wall,
    const float* __restrict__ b0p,
    const float* __restrict__ b1p,
    const float* __restrict__ b2p,
    __half* __restrict__ q_out,
    __half* __restrict__ k_out,
    __half* __restrict__ v_out)
{
    extern __shared__ __align__(16) __half smh[];
    const uint32_t smb = smem_u32(smh);

    const int z = blockIdx.z;
    const __half* W = Wall + (size_t)z * NE * NE;
    const float* bias = (z == 0) ? b0p : (z == 1) ? b1p : b2p;
    __half* out = (z == 0) ? q_out : (z == 1) ? k_out : v_out;
    const float oscale = (z == 0) ? ESCALE_F : 1.0f;

    const int tid = threadIdx.x;
    const int wid = tid >> 5;
    const int lane = tid & 31;
    const int g  = lane >> 2;
    const int tg = lane & 3;
    const int warpM = wid & 3;
    const int warpN = wid >> 2;
    const int bM = blockIdx.y * 128;
    const int bN = blockIdx.x * 128;

    const uint32_t aOff2 =
        (uint32_t)(((lane & 7) + ((lane >> 3) & 1) * 8) * RPADH +
                   ((lane >> 3) >> 1) * 8) * 2;
    const uint32_t bOff2 =
        (uint32_t)((lane & 7) * RPADH + (lane >> 3) * 8) * 2;

    auto load_stage = [&](int stage, int k0) {
        uint32_t dA = smb + (uint32_t)(stage * 2 * TILE_H) * 2;
        uint32_t dB = dA + (uint32_t)TILE_H * 2;
#pragma unroll
        for (int i = 0; i < 4; i++) {
            int c = tid + 256 * i;
            int row = c >> 3;
            int kq = (c & 7) << 3;
            uint32_t doff = (uint32_t)(row * RPADH + kq) * 2;
            cp_async16(dA + doff, &A[(size_t)(bM + row) * NE + k0 + kq]);
            cp_async16(dB + doff, &W[(size_t)(bN + row) * NE + k0 + kq]);
        }
        CP_COMMIT();
    };

    float acc[2][8][4];
#pragma unroll
    for (int mt = 0; mt < 2; mt++)
#pragma unroll
        for (int nt = 0; nt < 8; nt++)
#pragma unroll
            for (int r = 0; r < 4; r++) acc[mt][nt][r] = 0.f;

    load_stage(0, 0);
    load_stage(1, KSTEP);

    const int NKT = NE / KSTEP;    // 16
    for (int kt = 0; kt < NKT; kt++) {
        int st = kt % PROJ_STAGES;
        if (kt + 1 < NKT) { CP_WAIT(1); } else { CP_WAIT(0); }
        __syncthreads();
        if (kt + 2 < NKT)
            load_stage((kt + 2) % PROJ_STAGES, (kt + 2) * KSTEP);

        uint32_t sA_a = smb + (uint32_t)(st * 2 * TILE_H) * 2;
        uint32_t sB_a = sA_a + (uint32_t)TILE_H * 2;

        // A fragments: 4 k16-groups x 2 m-tiles, one LDSM.x4 each
        uint32_t aw[4][2][4];
#pragma unroll
        for (int j = 0; j < 4; j++)
#pragma unroll
            for (int mt = 0; mt < 2; mt++) {
                uint32_t base = sA_a +
                    (uint32_t)((warpM * 32 + mt * 16) * RPADH + j * 16) * 2;
                LDSM_X4(aw[j][mt], base + aOff2);
            }

#pragma unroll
        for (int nt = 0; nt < 8; nt++) {
            uint32_t kb[8];
            uint32_t base = sB_a +
                (uint32_t)((warpN * 64 + nt * 8) * RPADH) * 2;
            LDSM_X4(kb, base + bOff2);            // k-octets 0-3
            LDSM_X4(kb + 4, base + 64 + bOff2);   // k-octets 4-7 (+32 halves)
#pragma unroll
            for (int mt = 0; mt < 2; mt++)
#pragma unroll
                for (int j = 0; j < 4; j++)
                    mma_f16(acc[mt][nt], aw[j][mt][0], aw[j][mt][1],
                            aw[j][mt][2], aw[j][mt][3],
                            kb[2 * j], kb[2 * j + 1]);
        }
    }

    // Epilogue: bias, (Q: *ESCALE), fp16 round, scatter to [b,h,s,d]
#pragma unroll
    for (int mt = 0; mt < 2; mt++) {
        int r0 = bM + warpM * 32 + mt * 16 + g;
#pragma unroll
        for (int half_i = 0; half_i < 2; half_i++) {
            int m = r0 + 8 * half_i;
            int bb = m >> 11;
            int s = m & (NS - 1);
#pragma unroll
            for (int nt = 0; nt < 8; nt++) {
                int n = bN + warpN * 64 + nt * 8 + 2 * tg;
                int h = n >> 6;
                int d = n & 63;
                float v0 = (acc[mt][nt][2 * half_i + 0] + bias[n + 0]) * oscale;
                float v1 = (acc[mt][nt][2 * half_i + 1] + bias[n + 1]) * oscale;
                size_t idx = (((size_t)(bb * NH + h) * NS + s) * ND) + d;
                *(__half2*)&out[idx] = __floats2half2_rn(v0, v1);
            }
        }
    }
}

// ---------------------------------------------------------------------------
// fp16 flash attention: LDSM fragments, no online max, 3-stage KV pipeline,
// single barrier per tile, S pre-scaled (Q carries ESCALE).
// NEW: QK^T uses fp16-ACCUMULATE mma — S lands already packed in the fp16
// A-fragment layout, eliminating the 16 cvt/pack ops per tile on the
// serial path. Mask edits packed halves (diag tile only). P = ex2.f16x2
// directly on accumulators. l via ones-column f32-acc mma.
// 64-row q-tile, 128 threads, 3 blocks/SM.
// ---------------------------------------------------------------------------
#define HST 72
#define Q_HALVES (64 * HST)
#define KV_STAGE_H (2 * 64 * HST)
#define ATTN_STAGES 3
#define ATTN_SMEM ((Q_HALVES + ATTN_STAGES * KV_STAGE_H) * (int)sizeof(__half)) // 64512 B
#define ONES_H2 0x3C003C00u
#define NEGINF_H 0xFC00u

__global__ __launch_bounds__(128) void attn_mma_kernel(
    const int* __restrict__ is_masked_p,
    float* __restrict__ out)
{
    extern __shared__ __align__(16) __half smh[];
    const uint32_t smb = smem_u32(smh);

    const int qt = (int)(gridDim.x - 1 - blockIdx.x);   // heavy blocks first
    const int h = blockIdx.y, b = blockIdx.z;
    const int tid = threadIdx.x;
    const int wid = tid >> 5, lane = tid & 31;
    const int g = lane >> 2, tg = lane & 3;
    const int m0 = wid * 16;

    const size_t head = (size_t)(b * NH + h) * NS * ND;
    const __half* Qb = g_qh + head;
    const __half* Kb = g_kh + head;
    const __half* Vb = g_vh + head;

    const bool masked = (*is_masked_p) != 0;
    const int ntiles = masked ? (qt + 1) : (NS / 64);

    const uint32_t kOff2 = (uint32_t)((lane & 7) * HST + (lane >> 3) * 8) * 2;
    const uint32_t vOff2 = (uint32_t)(((lane >> 3) * 8 + (lane & 7)) * HST) * 2;

    auto kv_base = [&](int st) {
        return smb + (uint32_t)(Q_HALVES + st * KV_STAGE_H) * 2;
    };

    auto prefetch = [&](int t) {
        int st = t % ATTN_STAGES;
        uint32_t dK = kv_base(st);
        uint32_t dV = dK + (uint32_t)(64 * HST) * 2;
#pragma unroll
        for (int i = 0; i < 4; i++) {
            int c = tid + 128 * i;
            int r = c >> 3;
            int cq = (c & 7) << 3;
            uint32_t doff = (uint32_t)(r * HST + cq) * 2;
            cp_async16(dK + doff, &Kb[(size_t)(t * 64 + r) * ND + cq]);
            cp_async16(dV + doff, &Vb[(size_t)(t * 64 + r) * ND + cq]);
        }
        CP_COMMIT();
    };

    // Group 0: Q tile + KV tile 0; group 1: KV tile 1 (if any)
    {
        uint32_t dQ = smb;
#pragma unroll
        for (int i = 0; i < 4; i++) {
            int c = tid + 128 * i;
            int r = c >> 3;
            int cq = (c & 7) << 3;
            cp_async16(dQ + (uint32_t)(r * HST + cq) * 2,
                       &Qb[(size_t)(qt * 64 + r) * ND + cq]);
        }
    }
    prefetch(0);
    if (ntiles > 1) prefetch(1);

    uint32_t aQ[4][4];
    float o[8][4];
    float oL[4];   // l accumulator (all-ones B): every col = row sum
#pragma unroll
    for (int nt = 0; nt < 8; nt++)
#pragma unroll
        for (int r = 0; r < 4; r++) o[nt][r] = 0.f;
#pragma unroll
    for (int r = 0; r < 4; r++) oL[r] = 0.f;

    const int rg0 = qt * 64 + m0 + g;
    const int rg1 = rg0 + 8;

    for (int t = 0; t < ntiles; t++) {
        const int st = t % ATTN_STAGES;
        if (t + 1 < ntiles) { CP_WAIT(1); } else { CP_WAIT(0); }
        __syncthreads();
        if (t + 2 < ntiles) prefetch(t + 2);

        if (t == 0) {
            uint32_t qOff2 =
                (uint32_t)(((lane & 7) + ((lane >> 3) & 1) * 8) * HST +
                           ((lane >> 3) >> 1) * 8) * 2;
#pragma unroll
            for (int j = 0; j < 4; j++) {
                uint32_t base = smb + (uint32_t)(m0 * HST + j * 16) * 2;
                LDSM_X4(aQ[j], base + qOff2);
            }
        }

        uint32_t dK = kv_base(st);
        uint32_t dV = dK + (uint32_t)(64 * HST) * 2;

        // S = Qs K^T with fp16 accumulate: sh[nt][0] = {row g, cols 2tg,2tg+1},
        // sh[nt][1] = {row g+8, ...} — already in A-fragment layout.
        uint32_t sh[8][2];
#pragma unroll
        for (int nt = 0; nt < 8; nt++) {
            sh[nt][0] = 0u; sh[nt][1] = 0u;
            uint32_t kb[8];
            uint32_t base = dK + (uint32_t)(nt * 8 * HST) * 2;
            LDSM_X4(kb, base + kOff2);
            LDSM_X4(kb + 4, base + 64 + kOff2);
#pragma unroll
            for (int j = 0; j < 4; j++)
                mma_f16c(sh[nt], aQ[j][0], aQ[j][1], aQ[j][2], aQ[j][3],
                         kb[2 * j], kb[2 * j + 1]);
        }

        // Mask diag tile: set masked packed halves to -inf (ex2 -> 0)
        const bool diag = masked && (t == qt);
        if (diag) {
#pragma unroll
            for (int nt = 0; nt < 8; nt++) {
                int cg = t * 64 + nt * 8 + 2 * tg;
                uint32_t v0 = sh[nt][0], v1 = sh[nt][1];
                if (cg > rg0)     v0 = (v0 & 0xFFFF0000u) | NEGINF_H;
                if (cg + 1 > rg0) v0 = (v0 & 0x0000FFFFu) | (NEGINF_H << 16);
                if (cg > rg1)     v1 = (v1 & 0xFFFF0000u) | NEGINF_H;
                if (cg + 1 > rg1) v1 = (v1 & 0x0000FFFFu) | (NEGINF_H << 16);
                sh[nt][0] = v0; sh[nt][1] = v1;
            }
        }

        // P = ex2(S) directly on packed accumulators (MUFU f16x2)
        uint32_t pa[4][4];
#pragma unroll
        for (int j = 0; j < 4; j++) {
            pa[j][0] = h2ex2(sh[2 * j][0]);
            pa[j][1] = h2ex2(sh[2 * j][1]);
            pa[j][2] = h2ex2(sh[2 * j + 1][0]);
            pa[j][3] = h2ex2(sh[2 * j + 1][1]);
        }

        // O += P V ; l += P 1  (ones-column mma, fp32 acc)
#pragma unroll
        for (int nt = 0; nt < 8; nt++) {
            uint32_t vb[8];
            uint32_t base = dV + (uint32_t)(nt * 8) * 2;
            LDSM_X4T(vb, base + vOff2);
            LDSM_X4T(vb + 4, base + (uint32_t)(32 * HST) * 2 + vOff2);
#pragma unroll
            for (int j = 0; j < 4; j++)
                mma_f16(o[nt], pa[j][0], pa[j][1], pa[j][2], pa[j][3],
                        vb[2 * j], vb[2 * j + 1]);
        }
#pragma unroll
        for (int j = 0; j < 4; j++)
            mma_f16(oL, pa[j][0], pa[j][1], pa[j][2], pa[j][3],
                    ONES_H2, ONES_H2);
    }

    // Epilogue: l replicated in every accumulator column of oL
    float inv0 = 1.f / oL[0], inv1 = 1.f / oL[2];
    size_t base0 = ((size_t)b * NS + rg0) * NE + h * ND;
    size_t base1 = ((size_t)b * NS + rg1) * NE + h * ND;
#pragma unroll
    for (int nt = 0; nt < 8; nt++) {
        int cc = nt * 8 + 2 * tg;
        *(float2*)&out[base0 + cc] = make_float2(o[nt][0] * inv0, o[nt][1] * inv0);
        *(float2*)&out[base1 + cc] = make_float2(o[nt][2] * inv1, o[nt][3] * inv1);
    }
}

// ---------------------------------------------------------------------------
// Host
// ---------------------------------------------------------------------------
extern "C" void kernel_launch(void* const* d_in, const int* in_sizes, int n_in,
                              void* d_out, int out_size)
{
    const float* x     = (const float*)d_in[0];
    const float* Wq_w  = (const float*)d_in[1];
    const float* Wq_b  = (const float*)d_in[2];
    const float* Wk_w  = (const float*)d_in[3];
    const float* Wk_b  = (const float*)d_in[4];
    const float* Wv_w  = (const float*)d_in[5];
    const float* Wv_b  = (const float*)d_in[6];
    const int*   is_masked = (const int*)d_in[7];
    float* out = (float*)d_out;
    (void)in_sizes; (void)n_in; (void)out_size;

    void *p_xh, *p_wh, *p_qh, *p_kh, *p_vh;
    cudaGetSymbolAddress(&p_xh, g_xh);
    cudaGetSymbolAddress(&p_wh, g_wh);
    cudaGetSymbolAddress(&p_qh, g_qh);
    cudaGetSymbolAddress(&p_kh, g_kh);
    cudaGetSymbolAddress(&p_vh, g_vh);

    round_f16_kernel<<<(TOTAL4 + 511) / 512, 256>>>(
        (const float4*)x, (uint2*)p_xh,
        (const float4*)Wq_w, (const float4*)Wk_w, (const float4*)Wv_w,
        (uint2*)p_wh);

    cudaFuncSetAttribute(proj_mma_kernel,
                         cudaFuncAttributeMaxDynamicSharedMemorySize, PROJ_SMEM);
    cudaFuncSetAttribute(attn_mma_kernel,
                         cudaFuncAttributeMaxDynamicSharedMemorySize, ATTN_SMEM);

    dim3 gg(NE / 128, NM / 128, 3);   // (8, 32, 3) — fused Q/K/V
    proj_mma_kernel<<<gg, 256, PROJ_SMEM>>>((const __half*)p_xh, (const __half*)p_wh,
                                            Wq_b, Wk_b, Wv_b,
                                            (__half*)p_qh, (__half*)p_kh,
                                            (__half*)p_vh);

    dim3 ga(NS / 64, NH, NB);         // (32, 16, 2) — 1024 blocks, 128 thr
    attn_mma_kernel<<<ga, 128, ATTN_SMEM>>>(is_masked, out);
}

// round 17
// speedup vs baseline: 1.0326x; 1.0326x over previous
#include <cuda_runtime.h>
#include <cuda_fp16.h>
#include <cstdint>

// Problem constants
#define NB 2
#define NS 2048
#define NE 1024
#define NH 16
#define ND 64
#define NM (NB * NS)   // 4096 rows

// ---------------------------------------------------------------------------
// Static device scratch (fp16 operands; fp32 accumulation)
// ---------------------------------------------------------------------------
__device__ __align__(16) __half g_xh[(size_t)NM * NE];        // fp16 x
__device__ __align__(16) __half g_wh[3][(size_t)NE * NE];     // fp16 Wq/Wk/Wv
__device__ __align__(16) __half g_qh[(size_t)NM * NE];        // Q*ESCALE [b,h,s,d]
__device__ __align__(16) __half g_kh[(size_t)NM * NE];        // K [b,h,s,d]
__device__ __align__(16) __half g_vh[(size_t)NM * NE];        // V [b,h,s,d]

// ---------------------------------------------------------------------------
// Helpers
// ---------------------------------------------------------------------------
__device__ __forceinline__ uint32_t smem_u32(const void* p) {
    uint32_t a;
    asm("{ .reg .u64 t; cvta.to.shared.u64 t, %1; cvt.u32.u64 %0, t; }"
        : "=r"(a) : "l"(p));
    return a;
}

__device__ __forceinline__ void cp_async16(uint32_t dst, const void* src) {
    asm volatile("cp.async.cg.shared.global [%0], [%1], 16;"
                 :: "r"(dst), "l"(src) : "memory");
}
#define CP_COMMIT() asm volatile("cp.async.commit_group;" ::: "memory")
#define CP_WAIT(n)  asm volatile("cp.async.wait_group %0;" :: "n"(n) : "memory")

__device__ __forceinline__ uint32_t pack_h2(float lo, float hi) {
    uint32_t r;
    asm("cvt.rn.f16x2.f32 %0, %1, %2;" : "=r"(r) : "f"(hi), "f"(lo));
    return r;
}

// half2 exp2 on MUFU: two exps per instruction
__device__ __forceinline__ uint32_t h2ex2(uint32_t x) {
    uint32_t r;
    asm("ex2.approx.f16x2 %0, %1;" : "=r"(r) : "r"(x));
    return r;
}

// m16n8k16 fp16 mma, fp32 accumulate: D = A*B + D
__device__ __forceinline__ void mma_f16(float* c, uint32_t a0, uint32_t a1,
                                        uint32_t a2, uint32_t a3,
                                        uint32_t b0, uint32_t b1) {
    asm volatile(
        "mma.sync.aligned.m16n8k16.row.col.f32.f16.f16.f32 "
        "{%0,%1,%2,%3}, {%4,%5,%6,%7}, {%8,%9}, {%0,%1,%2,%3};"
        : "+f"(c[0]), "+f"(c[1]), "+f"(c[2]), "+f"(c[3])
        : "r"(a0), "r"(a1), "r"(a2), "r"(a3), "r"(b0), "r"(b1));
}

#define LDSM_X4(r, addr) \
    asm volatile("ldmatrix.sync.aligned.m8n8.x4.shared.b16 {%0,%1,%2,%3}, [%4];" \
                 : "=r"((r)[0]), "=r"((r)[1]), "=r"((r)[2]), "=r"((r)[3]) \
                 : "r"(addr))

#define LDSM_X4T(r, addr) \
    asm volatile("ldmatrix.sync.aligned.m8n8.x4.trans.shared.b16 {%0,%1,%2,%3}, [%4];" \
                 : "=r"((r)[0]), "=r"((r)[1]), "=r"((r)[2]), "=r"((r)[3]) \
                 : "r"(addr))

// ---------------------------------------------------------------------------
// Rounding pre-pass: fp32 -> fp16 (rn); single 8-byte store per float4.
// ---------------------------------------------------------------------------
#define XN4 (NM * NE / 4)
#define WN4 (NE * NE / 4)
#define TOTAL4 (XN4 + 3 * WN4)   // 1835008

__global__ __launch_bounds__(256) void round_f16_kernel(
    const float4* __restrict__ x,  uint2* __restrict__ xh,
    const float4* __restrict__ w0, const float4* __restrict__ w1,
    const float4* __restrict__ w2, uint2* __restrict__ wh)
{
#pragma unroll
    for (int u = 0; u < 2; u++) {
        int i = blockIdx.x * 512 + u * 256 + threadIdx.x;
        if (i >= TOTAL4) return;
        const float4* src;
        uint2* dst;
        if (i < XN4) {
            src = x + i; dst = xh + i;
        } else {
            int j = i - XN4;
            int wsel = j / WN4;
            int off = j - wsel * WN4;
            src = ((wsel == 0) ? w0 : (wsel == 1) ? w1 : w2) + off;
            dst = wh + (size_t)wsel * WN4 + off;
        }
        float4 v = *src;
        uint2 o;
        o.x = pack_h2(v.x, v.y);
        o.y = pack_h2(v.z, v.w);
        *dst = o;
    }
}

// ---------------------------------------------------------------------------
// Fused QKV projection, fp16 m16n8k16, LDSM loads, 3-stage cp.async pipeline,
// single barrier per K-step, K-step = 64 halves. (Known good.)
// ---------------------------------------------------------------------------
#define KSTEP 64
#define RPADH 72
#define TILE_H (128 * RPADH)
#define PROJ_STAGES 3
#define PROJ_SMEM (PROJ_STAGES * 2 * TILE_H * (int)sizeof(__half))  // 110592 B
#define ESCALE_F 0.1803368801111601f

__global__ __launch_bounds__(256, 2) void proj_mma_kernel(
    const __half* __restrict__ A,
    const __half* __restrict__ Wall,
    const float* __restrict__ b0p,
    const float* __restrict__ b1p,
    const float* __restrict__ b2p,
    __half* __restrict__ q_out,
    __half* __restrict__ k_out,
    __half* __restrict__ v_out)
{
    extern __shared__ __align__(16) __half smh[];
    const uint32_t smb = smem_u32(smh);

    const int z = blockIdx.z;
    const __half* W = Wall + (size_t)z * NE * NE;
    const float* bias = (z == 0) ? b0p : (z == 1) ? b1p : b2p;
    __half* out = (z == 0) ? q_out : (z == 1) ? k_out : v_out;
    const float oscale = (z == 0) ? ESCALE_F : 1.0f;

    const int tid = threadIdx.x;
    const int wid = tid >> 5;
    const int lane = tid & 31;
    const int g  = lane >> 2;
    const int tg = lane & 3;
    const int warpM = wid & 3;
    const int warpN = wid >> 2;
    const int bM = blockIdx.y * 128;
    const int bN = blockIdx.x * 128;

    const uint32_t aOff2 =
        (uint32_t)(((lane & 7) + ((lane >> 3) & 1) * 8) * RPADH +
                   ((lane >> 3) >> 1) * 8) * 2;
    const uint32_t bOff2 =
        (uint32_t)((lane & 7) * RPADH + (lane >> 3) * 8) * 2;

    auto load_stage = [&](int stage, int k0) {
        uint32_t dA = smb + (uint32_t)(stage * 2 * TILE_H) * 2;
        uint32_t dB = dA + (uint32_t)TILE_H * 2;
#pragma unroll
        for (int i = 0; i < 4; i++) {
            int c = tid + 256 * i;
            int row = c >> 3;
            int kq = (c & 7) << 3;
            uint32_t doff = (uint32_t)(row * RPADH + kq) * 2;
            cp_async16(dA + doff, &A[(size_t)(bM + row) * NE + k0 + kq]);
            cp_async16(dB + doff, &W[(size_t)(bN + row) * NE + k0 + kq]);
        }
        CP_COMMIT();
    };

    float acc[2][8][4];
#pragma unroll
    for (int mt = 0; mt < 2; mt++)
#pragma unroll
        for (int nt = 0; nt < 8; nt++)
#pragma unroll
            for (int r = 0; r < 4; r++) acc[mt][nt][r] = 0.f;

    load_stage(0, 0);
    load_stage(1, KSTEP);

    const int NKT = NE / KSTEP;    // 16
    for (int kt = 0; kt < NKT; kt++) {
        int st = kt % PROJ_STAGES;
        if (kt + 1 < NKT) { CP_WAIT(1); } else { CP_WAIT(0); }
        __syncthreads();
        if (kt + 2 < NKT)
            load_stage((kt + 2) % PROJ_STAGES, (kt + 2) * KSTEP);

        uint32_t sA_a = smb + (uint32_t)(st * 2 * TILE_H) * 2;
        uint32_t sB_a = sA_a + (uint32_t)TILE_H * 2;

        // A fragments: 4 k16-groups x 2 m-tiles, one LDSM.x4 each
        uint32_t aw[4][2][4];
#pragma unroll
        for (int j = 0; j < 4; j++)
#pragma unroll
            for (int mt = 0; mt < 2; mt++) {
                uint32_t base = sA_a +
                    (uint32_t)((warpM * 32 + mt * 16) * RPADH + j * 16) * 2;
                LDSM_X4(aw[j][mt], base + aOff2);
            }

#pragma unroll
        for (int nt = 0; nt < 8; nt++) {
            uint32_t kb[8];
            uint32_t base = sB_a +
                (uint32_t)((warpN * 64 + nt * 8) * RPADH) * 2;
            LDSM_X4(kb, base + bOff2);            // k-octets 0-3
            LDSM_X4(kb + 4, base + 64 + bOff2);   // k-octets 4-7 (+32 halves)
#pragma unroll
            for (int mt = 0; mt < 2; mt++)
#pragma unroll
                for (int j = 0; j < 4; j++)
                    mma_f16(acc[mt][nt], aw[j][mt][0], aw[j][mt][1],
                            aw[j][mt][2], aw[j][mt][3],
                            kb[2 * j], kb[2 * j + 1]);
        }
    }

    // Epilogue: bias, (Q: *ESCALE), fp16 round, scatter to [b,h,s,d]
#pragma unroll
    for (int mt = 0; mt < 2; mt++) {
        int r0 = bM + warpM * 32 + mt * 16 + g;
#pragma unroll
        for (int half_i = 0; half_i < 2; half_i++) {
            int m = r0 + 8 * half_i;
            int bb = m >> 11;
            int s = m & (NS - 1);
#pragma unroll
            for (int nt = 0; nt < 8; nt++) {
                int n = bN + warpN * 64 + nt * 8 + 2 * tg;
                int h = n >> 6;
                int d = n & 63;
                float v0 = (acc[mt][nt][2 * half_i + 0] + bias[n + 0]) * oscale;
                float v1 = (acc[mt][nt][2 * half_i + 1] + bias[n + 1]) * oscale;
                size_t idx = (((size_t)(bb * NH + h) * NS + s) * ND) + d;
                *(__half2*)&out[idx] = __floats2half2_rn(v0, v1);
            }
        }
    }
}

// ---------------------------------------------------------------------------
// fp16 flash attention (best-known configuration): LDSM fragments, no online
// max, 3-stage KV pipeline, single barrier per tile, S pre-scaled (Q carries
// ESCALE), P via ex2.f16x2 on packed fragments, l via ones-column mma
// (replicated row sum in accumulator). 64-row q-tile, 128 threads,
// 3 blocks/SM.
// ---------------------------------------------------------------------------
#define HST 72
#define Q_HALVES (64 * HST)
#define KV_STAGE_H (2 * 64 * HST)
#define ATTN_STAGES 3
#define ATTN_SMEM ((Q_HALVES + ATTN_STAGES * KV_STAGE_H) * (int)sizeof(__half)) // 64512 B
#define ONES_H2 0x3C003C00u

__global__ __launch_bounds__(128) void attn_mma_kernel(
    const int* __restrict__ is_masked_p,
    float* __restrict__ out)
{
    extern __shared__ __align__(16) __half smh[];
    const uint32_t smb = smem_u32(smh);

    const int qt = (int)(gridDim.x - 1 - blockIdx.x);   // heavy blocks first
    const int h = blockIdx.y, b = blockIdx.z;
    const int tid = threadIdx.x;
    const int wid = tid >> 5, lane = tid & 31;
    const int g = lane >> 2, tg = lane & 3;
    const int m0 = wid * 16;

    const size_t head = (size_t)(b * NH + h) * NS * ND;
    const __half* Qb = g_qh + head;
    const __half* Kb = g_kh + head;
    const __half* Vb = g_vh + head;

    const bool masked = (*is_masked_p) != 0;
    const int ntiles = masked ? (qt + 1) : (NS / 64);

    const uint32_t kOff2 = (uint32_t)((lane & 7) * HST + (lane >> 3) * 8) * 2;
    const uint32_t vOff2 = (uint32_t)(((lane >> 3) * 8 + (lane & 7)) * HST) * 2;

    auto kv_base = [&](int st) {
        return smb + (uint32_t)(Q_HALVES + st * KV_STAGE_H) * 2;
    };

    auto prefetch = [&](int t) {
        int st = t % ATTN_STAGES;
        uint32_t dK = kv_base(st);
        uint32_t dV = dK + (uint32_t)(64 * HST) * 2;
#pragma unroll
        for (int i = 0; i < 4; i++) {
            int c = tid + 128 * i;
            int r = c >> 3;
            int cq = (c & 7) << 3;
            uint32_t doff = (uint32_t)(r * HST + cq) * 2;
            cp_async16(dK + doff, &Kb[(size_t)(t * 64 + r) * ND + cq]);
            cp_async16(dV + doff, &Vb[(size_t)(t * 64 + r) * ND + cq]);
        }
        CP_COMMIT();
    };

    // Group 0: Q tile + KV tile 0; group 1: KV tile 1 (if any)
    {
        uint32_t dQ = smb;
#pragma unroll
        for (int i = 0; i < 4; i++) {
            int c = tid + 128 * i;
            int r = c >> 3;
            int cq = (c & 7) << 3;
            cp_async16(dQ + (uint32_t)(r * HST + cq) * 2,
                       &Qb[(size_t)(qt * 64 + r) * ND + cq]);
        }
    }
    prefetch(0);
    if (ntiles > 1) prefetch(1);

    uint32_t aQ[4][4];
    float o[8][4];
    float oL[4];   // l accumulator (all-ones B): every col = row sum
#pragma unroll
    for (int nt = 0; nt < 8; nt++)
#pragma unroll
        for (int r = 0; r < 4; r++) o[nt][r] = 0.f;
#pragma unroll
    for (int r = 0; r < 4; r++) oL[r] = 0.f;

    const int rg0 = qt * 64 + m0 + g;
    const int rg1 = rg0 + 8;

    for (int t = 0; t < ntiles; t++) {
        const int st = t % ATTN_STAGES;
        if (t + 1 < ntiles) { CP_WAIT(1); } else { CP_WAIT(0); }
        __syncthreads();
        if (t + 2 < ntiles) prefetch(t + 2);

        if (t == 0) {
            uint32_t qOff2 =
                (uint32_t)(((lane & 7) + ((lane >> 3) & 1) * 8) * HST +
                           ((lane >> 3) >> 1) * 8) * 2;
#pragma unroll
            for (int j = 0; j < 4; j++) {
                uint32_t base = smb + (uint32_t)(m0 * HST + j * 16) * 2;
                LDSM_X4(aQ[j], base + qOff2);
            }
        }

        uint32_t dK = kv_base(st);
        uint32_t dV = dK + (uint32_t)(64 * HST) * 2;

        // S = Qs K^T  (pre-scaled: Q carries 0.125*log2e)
        float s[8][4];
#pragma unroll
        for (int nt = 0; nt < 8; nt++) {
#pragma unroll
            for (int r = 0; r < 4; r++) s[nt][r] = 0.f;
            uint32_t kb[8];
            uint32_t base = dK + (uint32_t)(nt * 8 * HST) * 2;
            LDSM_X4(kb, base + kOff2);
            LDSM_X4(kb + 4, base + 64 + kOff2);
#pragma unroll
            for (int j = 0; j < 4; j++)
                mma_f16(s[nt], aQ[j][0], aQ[j][1], aQ[j][2], aQ[j][3],
                        kb[2 * j], kb[2 * j + 1]);
        }

        // Mask diag tile (-1e9 -> fp16 -inf -> ex2 -> 0)
        const bool diag = masked && (t == qt);
        if (diag) {
#pragma unroll
            for (int nt = 0; nt < 8; nt++) {
                int cg = t * 64 + nt * 8 + 2 * tg;
                if (cg > rg0)     s[nt][0] = -1e9f;
                if (cg + 1 > rg0) s[nt][1] = -1e9f;
                if (cg > rg1)     s[nt][2] = -1e9f;
                if (cg + 1 > rg1) s[nt][3] = -1e9f;
            }
        }

        // P = ex2(S) in fp16: pack to A-fragment layout, then half2 MUFU exp
        uint32_t pa[4][4];
#pragma unroll
        for (int j = 0; j < 4; j++) {
            pa[j][0] = h2ex2(pack_h2(s[2 * j][0],     s[2 * j][1]));
            pa[j][1] = h2ex2(pack_h2(s[2 * j][2],     s[2 * j][3]));
            pa[j][2] = h2ex2(pack_h2(s[2 * j + 1][0], s[2 * j + 1][1]));
            pa[j][3] = h2ex2(pack_h2(s[2 * j + 1][2], s[2 * j + 1][3]));
        }

        // O += P V ; l += P 1  (ones-column mma)
#pragma unroll
        for (int nt = 0; nt < 8; nt++) {
            uint32_t vb[8];
            uint32_t base = dV + (uint32_t)(nt * 8) * 2;
            LDSM_X4T(vb, base + vOff2);
            LDSM_X4T(vb + 4, base + (uint32_t)(32 * HST) * 2 + vOff2);
#pragma unroll
            for (int j = 0; j < 4; j++)
                mma_f16(o[nt], pa[j][0], pa[j][1], pa[j][2], pa[j][3],
                        vb[2 * j], vb[2 * j + 1]);
        }
#pragma unroll
        for (int j = 0; j < 4; j++)
            mma_f16(oL, pa[j][0], pa[j][1], pa[j][2], pa[j][3],
                    ONES_H2, ONES_H2);
    }

    // Epilogue: l replicated in every accumulator column of oL
    float inv0 = 1.f / oL[0], inv1 = 1.f / oL[2];
    size_t base0 = ((size_t)b * NS + rg0) * NE + h * ND;
    size_t base1 = ((size_t)b * NS + rg1) * NE + h * ND;
#pragma unroll
    for (int nt = 0; nt < 8; nt++) {
        int cc = nt * 8 + 2 * tg;
        *(float2*)&out[base0 + cc] = make_float2(o[nt][0] * inv0, o[nt][1] * inv0);
        *(float2*)&out[base1 + cc] = make_float2(o[nt][2] * inv1, o[nt][3] * inv1);
    }
}

// ---------------------------------------------------------------------------
// Host
// ---------------------------------------------------------------------------
extern "C" void kernel_launch(void* const* d_in, const int* in_sizes, int n_in,
                              void* d_out, int out_size)
{
    const float* x     = (const float*)d_in[0];
    const float* Wq_w  = (const float*)d_in[1];
    const float* Wq_b  = (const float*)d_in[2];
    const float* Wk_w  = (const float*)d_in[3];
    const float* Wk_b  = (const float*)d_in[4];
    const float* Wv_w  = (const float*)d_in[5];
    const float* Wv_b  = (const float*)d_in[6];
    const int*   is_masked = (const int*)d_in[7];
    float* out = (float*)d_out;
    (void)in_sizes; (void)n_in; (void)out_size;

    void *p_xh, *p_wh, *p_qh, *p_kh, *p_vh;
    cudaGetSymbolAddress(&p_xh, g_xh);
    cudaGetSymbolAddress(&p_wh, g_wh);
    cudaGetSymbolAddress(&p_qh, g_qh);
    cudaGetSymbolAddress(&p_kh, g_kh);
    cudaGetSymbolAddress(&p_vh, g_vh);

    round_f16_kernel<<<(TOTAL4 + 511) / 512, 256>>>(
        (const float4*)x, (uint2*)p_xh,
        (const float4*)Wq_w, (const float4*)Wk_w, (const float4*)Wv_w,
        (uint2*)p_wh);

    cudaFuncSetAttribute(proj_mma_kernel,
                         cudaFuncAttributeMaxDynamicSharedMemorySize, PROJ_SMEM);
    cudaFuncSetAttribute(attn_mma_kernel,
                         cudaFuncAttributeMaxDynamicSharedMemorySize, ATTN_SMEM);

    dim3 gg(NE / 128, NM / 128, 3);   // (8, 32, 3) — fused Q/K/V
    proj_mma_kernel<<<gg, 256, PROJ_SMEM>>>((const __half*)p_xh, (const __half*)p_wh,
                                            Wq_b, Wk_b, Wv_b,
                                            (__half*)p_qh, (__half*)p_kh,
                                            (__half*)p_vh);

    dim3 ga(NS / 64, NH, NB);         // (32, 16, 2) — 1024 blocks, 128 thr
    attn_mma_kernel<<<ga, 128, ATTN_SMEM>>>(is_masked, out);
}